// round 14
// baseline (speedup 1.0000x reference)
#include <cuda_runtime.h>
#include <math.h>

#define LSEQ 5000
#define NB 2
#define NE 20
#define NH 5
#define ND 4
#define NFF 120
#define NDEC 40
#define KW 50
#define CPAD 25
#define NBH (NB*NH)

// ---------------- device scratch (no allocations allowed) ----------------
__device__ __align__(16) float g_h[NB*LSEQ*NE];   // residual stream (B,L,E)
__device__ __align__(16) float g_q[NBH*LSEQ*ND];  // (B,H,L,D)
__device__ __align__(16) float g_k[NBH*LSEQ*ND];
__device__ __align__(16) float g_v[NBH*LSEQ*ND];
__device__ __align__(16) float g_o[NB*LSEQ*NE];   // attention output (B,L,E)

// freq[e] = 10000^(-e/10) = 10^(-0.4 e)  (both even/odd rows reduce to exponent e/10)
__constant__ double c_freq[NE] = {
    1.0,
    0.39810717055349725, 0.15848931924611134, 0.06309573444801933,
    0.025118864315095794, 0.01,
    0.0039810717055349725, 0.0015848931924611134, 0.0006309573444801933,
    0.00025118864315095795, 1e-4,
    3.9810717055349725e-05, 1.5848931924611134e-05, 6.309573444801933e-06,
    2.5118864315095795e-06, 1e-06,
    3.9810717055349725e-07, 1.5848931924611134e-07, 6.309573444801933e-08,
    2.5118864315095795e-08
};

// FMA-pipe exp2 for x <= 0 (avoids MUFU bottleneck). Max rel err ~1.3e-6.
__device__ __forceinline__ float exp2p(float x) {
    x = fmaxf(x, -126.0f);
    float fl = floorf(x);
    float f = x - fl;                 // [0,1)
    float p = 1.5252734e-5f;
    p = fmaf(p, f, 1.5403530e-4f);
    p = fmaf(p, f, 1.3333558e-3f);
    p = fmaf(p, f, 9.6181291e-3f);
    p = fmaf(p, f, 5.5504109e-2f);
    p = fmaf(p, f, 2.4022651e-1f);
    p = fmaf(p, f, 6.9314718e-1f);
    p = fmaf(p, f, 1.0f);
    int n = (int)fl;
    return __int_as_float((n + 127) << 23) * p;
}

// ---------------- conv embed + positional encoding ----------------
__global__ void conv_pe_kernel(const float* __restrict__ x, const float* __restrict__ w)
{
    __shared__ float ws[NE*KW];
    __shared__ float xs[128 + KW - 1];
    int b  = blockIdx.y;
    int l0 = blockIdx.x * 128;
    int t  = threadIdx.x;
    for (int i = t; i < NE*KW; i += 128) ws[i] = w[i];
    for (int i = t; i < 128 + KW - 1; i += 128) {
        int g = l0 - CPAD + i;
        xs[i] = (g >= 0 && g < LSEQ) ? x[b*LSEQ + g] : 0.f;
    }
    __syncthreads();
    int l = l0 + t;
    if (l >= LSEQ) return;

    float xr[KW];
    #pragma unroll
    for (int k = 0; k < KW; k++) xr[k] = xs[t + k];

    float* hrow = g_h + (b*LSEQ + l)*NE;
    double pos = (double)l;
    #pragma unroll
    for (int e = 0; e < NE; e++) {
        float a = 0.f;
        #pragma unroll
        for (int k = 0; k < KW; k++) a = fmaf(xr[k], ws[e*KW + k], a);
        // double-precision range reduction, then fp32 sin/cos
        double arg = pos * c_freq[e];
        double kq  = rint(arg * 0.15915494309189535);  // /(2*pi)
        float red  = (float)fma(kq, -6.283185307179586, arg);
        float pe   = (e & 1) ? cosf(red) : sinf(red);
        hrow[e] = a + pe;
    }
}

// ---------------- QKV projection (per-head 4x4), scale*log2e folded into Q ----------------
__global__ void qkv_kernel(const float* __restrict__ wq, const float* __restrict__ wk,
                           const float* __restrict__ wv)
{
    int idx = blockIdx.x * blockDim.x + threadIdx.x;
    if (idx >= NBH*LSEQ) return;
    int l  = idx % LSEQ;
    int bh = idx / LSEQ;       // b*NH + h
    int h  = bh % NH;
    int b  = bh / NH;

    const float4 s = *(const float4*)(g_h + (b*LSEQ + l)*NE + h*ND);
    const float QS = 0.32260195918f;  // log2(e)/sqrt(20)

    float qo[4], ko[4], vo[4];
    #pragma unroll
    for (int d = 0; d < 4; d++) {
        qo[d] = (s.x*wq[d*4+0] + s.y*wq[d*4+1] + s.z*wq[d*4+2] + s.w*wq[d*4+3]) * QS;
        ko[d] =  s.x*wk[d*4+0] + s.y*wk[d*4+1] + s.z*wk[d*4+2] + s.w*wk[d*4+3];
        vo[d] =  s.x*wv[d*4+0] + s.y*wv[d*4+1] + s.z*wv[d*4+2] + s.w*wv[d*4+3];
    }
    int off = (bh*LSEQ + l);
    ((float4*)g_q)[off] = make_float4(qo[0], qo[1], qo[2], qo[3]);
    ((float4*)g_k)[off] = make_float4(ko[0], ko[1], ko[2], ko[3]);
    ((float4*)g_v)[off] = make_float4(vo[0], vo[1], vo[2], vo[3]);
}

// ---------------- flash attention, D=4, online softmax in log2 domain ----------------
__global__ void attn_kernel()
{
    __shared__ float4 ks[128], vs[128];
    int bh = blockIdx.y;
    int q0 = blockIdx.x * 128;
    int t  = threadIdx.x;
    int qi = q0 + t;

    const float4* qp = ((const float4*)g_q) + bh*LSEQ;
    const float4* kp = ((const float4*)g_k) + bh*LSEQ;
    const float4* vp = ((const float4*)g_v) + bh*LSEQ;

    float4 q = (qi < LSEQ) ? qp[qi] : make_float4(0.f, 0.f, 0.f, 0.f);
    float m = -1e30f, lsum = 0.f;
    float a0 = 0.f, a1 = 0.f, a2 = 0.f, a3 = 0.f;

    for (int kt = 0; kt < LSEQ; kt += 128) {
        int kidx = kt + t;
        if (kidx < LSEQ) { ks[t] = kp[kidx]; vs[t] = vp[kidx]; }
        __syncthreads();
        int kn = min(128, LSEQ - kt);
        // tile-local partials (accuracy + shorter fp32 sum chains)
        float tl = 0.f, t0 = 0.f, t1 = 0.f, t2 = 0.f, t3 = 0.f;
        #pragma unroll 4
        for (int j = 0; j < kn; j++) {
            float4 kk = ks[j];
            float s = fmaf(q.x, kk.x, fmaf(q.y, kk.y, fmaf(q.z, kk.z, q.w*kk.w)));
            float e;
            if (s > m) {
                float c = exp2p(m - s);
                m = s;
                lsum *= c; a0 *= c; a1 *= c; a2 *= c; a3 *= c;
                tl   *= c; t0 *= c; t1 *= c; t2 *= c; t3 *= c;
                e = 1.f;
            } else {
                e = exp2p(s - m);
            }
            float4 vv = vs[j];
            tl += e;
            t0 = fmaf(e, vv.x, t0);
            t1 = fmaf(e, vv.y, t1);
            t2 = fmaf(e, vv.z, t2);
            t3 = fmaf(e, vv.w, t3);
        }
        lsum += tl; a0 += t0; a1 += t1; a2 += t2; a3 += t3;
        __syncthreads();
    }

    if (qi < LSEQ) {
        int b = bh / NH, h = bh % NH;
        float inv = 1.f / lsum;
        float* op = g_o + (b*LSEQ + qi)*NE + h*ND;
        *(float4*)op = make_float4(a0*inv, a1*inv, a2*inv, a3*inv);
    }
}

// ---------------- fused: out-proj + residual + LN_A + FF + residual + LN_B ----------------
__global__ void proj_ff_kernel(const float* __restrict__ Wc, const float* __restrict__ bc,
                               const float* __restrict__ ga, const float* __restrict__ ba,
                               const float* __restrict__ W1, const float* __restrict__ b1,
                               const float* __restrict__ W2, const float* __restrict__ b2,
                               const float* __restrict__ gb, const float* __restrict__ bb)
{
    __shared__ float orow[NE], hrow[NE], h1[NE], hid[NFF];
    int row = blockIdx.x;
    int t   = threadIdx.x;
    if (t < NE) { orow[t] = g_o[row*NE + t]; hrow[t] = g_h[row*NE + t]; }
    __syncthreads();

    float tv = 0.f;
    if (t < NE) {
        float a = bc[t] + hrow[t];
        #pragma unroll
        for (int e = 0; e < NE; e++) a = fmaf(orow[e], Wc[t*NE + e], a);
        tv = a;
    }
    if (t < 32) {  // warp 0: LN over 20 values via shuffles
        float s = (t < NE) ? tv : 0.f;
        #pragma unroll
        for (int o = 16; o; o >>= 1) s += __shfl_xor_sync(0xffffffffu, s, o);
        float mu = s * (1.0f/NE);
        float d  = (t < NE) ? (tv - mu) : 0.f;
        float s2 = d * d;
        #pragma unroll
        for (int o = 16; o; o >>= 1) s2 += __shfl_xor_sync(0xffffffffu, s2, o);
        float rstd = rsqrtf(s2 * (1.0f/NE) + 1e-5f);
        if (t < NE) h1[t] = d * rstd * ga[t] + ba[t];
    }
    __syncthreads();

    if (t < NFF) {
        float a = b1[t];
        #pragma unroll
        for (int e = 0; e < NE; e++) a = fmaf(h1[e], W1[t*NE + e], a);
        hid[t] = fmaxf(a, 0.f);
    }
    __syncthreads();

    float fv = 0.f;
    if (t < NE) {
        float a = b2[t] + h1[t];
        #pragma unroll 10
        for (int f = 0; f < NFF; f++) a = fmaf(hid[f], W2[t*NFF + f], a);
        fv = a;
    }
    if (t < 32) {
        float s = (t < NE) ? fv : 0.f;
        #pragma unroll
        for (int o = 16; o; o >>= 1) s += __shfl_xor_sync(0xffffffffu, s, o);
        float mu = s * (1.0f/NE);
        float d  = (t < NE) ? (fv - mu) : 0.f;
        float s2 = d * d;
        #pragma unroll
        for (int o = 16; o; o >>= 1) s2 += __shfl_xor_sync(0xffffffffu, s2, o);
        float rstd = rsqrtf(s2 * (1.0f/NE) + 1e-5f);
        if (t < NE) g_h[row*NE + t] = d * rstd * gb[t] + bb[t];
    }
}

// ---------------- decoder MLP: 20 -> 40 -> 40 -> 20 -> 1 (sigmoid) ----------------
__global__ void dec_kernel(const float* __restrict__ f1w, const float* __restrict__ f1b,
                           const float* __restrict__ f2w, const float* __restrict__ f2b,
                           const float* __restrict__ f3w, const float* __restrict__ f3b,
                           const float* __restrict__ f4w, const float* __restrict__ f4b,
                           float* __restrict__ out)
{
    __shared__ float hrow[NE], d1[NDEC], d2[NDEC], d3s[NE];
    int row = blockIdx.x;
    int t   = threadIdx.x;
    if (t < NE) hrow[t] = g_h[row*NE + t];
    __syncthreads();
    if (t < NDEC) {
        float a = f1b[t];
        #pragma unroll
        for (int e = 0; e < NE; e++) a = fmaf(hrow[e], f1w[t*NE + e], a);
        d1[t] = fmaxf(a, 0.f);
    }
    __syncthreads();
    if (t < NDEC) {
        float a = f2b[t];
        #pragma unroll
        for (int j = 0; j < NDEC; j++) a = fmaf(d1[j], f2w[t*NDEC + j], a);
        d2[t] = fmaxf(a, 0.f);
    }
    __syncthreads();
    if (t < NE) {
        float a = f3b[t];
        #pragma unroll
        for (int j = 0; j < NDEC; j++) a = fmaf(d2[j], f3w[t*NDEC + j], a);
        d3s[t] = fmaxf(a, 0.f);
    }
    __syncthreads();
    if (t == 0) {
        float a = f4b[0];
        #pragma unroll
        for (int e = 0; e < NE; e++) a = fmaf(d3s[e], f4w[e], a);
        out[row] = 1.f / (1.f + expf(-a));
    }
}

// ---------------- launch ----------------
extern "C" void kernel_launch(void* const* d_in, const int* in_sizes, int n_in,
                              void* d_out, int out_size)
{
    const float* x      = (const float*)d_in[0];
    const float* conv_w = (const float*)d_in[1];
    const float* Wv     = (const float*)d_in[2];
    const float* Wk     = (const float*)d_in[3];
    const float* Wq     = (const float*)d_in[4];
    const float* Wc     = (const float*)d_in[5];
    const float* bc     = (const float*)d_in[6];
    const float* lnAg   = (const float*)d_in[7];
    const float* lnAb   = (const float*)d_in[8];
    const float* W1     = (const float*)d_in[9];
    const float* b1     = (const float*)d_in[10];
    const float* W2     = (const float*)d_in[11];
    const float* b2     = (const float*)d_in[12];
    const float* lnBg   = (const float*)d_in[13];
    const float* lnBb   = (const float*)d_in[14];
    const float* f1w    = (const float*)d_in[15];
    const float* f1b    = (const float*)d_in[16];
    const float* f2w    = (const float*)d_in[17];
    const float* f2b    = (const float*)d_in[18];
    const float* f3w    = (const float*)d_in[19];
    const float* f3b    = (const float*)d_in[20];
    const float* f4w    = (const float*)d_in[21];
    const float* f4b    = (const float*)d_in[22];
    float* out = (float*)d_out;

    conv_pe_kernel<<<dim3((LSEQ + 127)/128, NB), 128>>>(x, conv_w);
    for (int i = 0; i < 4; i++) {
        qkv_kernel<<<(NBH*LSEQ + 127)/128, 128>>>(Wq + i*16, Wk + i*16, Wv + i*16);
        attn_kernel<<<dim3((LSEQ + 127)/128, NBH), 128>>>();
        proj_ff_kernel<<<NB*LSEQ, 128>>>(Wc + i*NE*NE, bc + i*NE,
                                         lnAg + i*NE, lnAb + i*NE,
                                         W1 + i*NFF*NE, b1 + i*NFF,
                                         W2 + i*NE*NFF, b2 + i*NE,
                                         lnBg + i*NE, lnBb + i*NE);
    }
    dec_kernel<<<NB*LSEQ, 64>>>(f1w, f1b, f2w, f2b, f3w, f3b, f4w, f4b, out);
}

// round 15
// speedup vs baseline: 1.9960x; 1.9960x over previous
#include <cuda_runtime.h>
#include <math.h>

#define LSEQ 5000
#define NB 2
#define NE 20
#define NH 5
#define ND 4
#define NFF 120
#define NDEC 40
#define KW 50
#define CPAD 25
#define NBH (NB*NH)
#define KSPLIT 5
#define KCHUNK (LSEQ/KSPLIT)   // 1000
#define KTILE 40               // KCHUNK % KTILE == 0

// ---------------- device scratch (no allocations allowed) ----------------
__device__ __align__(16) float g_h[NB*LSEQ*NE];          // residual stream (B,L,E)
__device__ __align__(16) float g_q[NBH*LSEQ*ND];         // (B,H,L,D)
__device__ __align__(16) float g_k[NBH*LSEQ*ND];
__device__ __align__(16) float g_v[NBH*LSEQ*ND];
__device__ __align__(16) float g_o[NB*LSEQ*NE];          // attention output (B,L,E)
__device__ __align__(16) float4 g_pacc[NBH*KSPLIT*LSEQ]; // split-K partial accumulators
__device__ __align__(16) float2 g_pml[NBH*KSPLIT*LSEQ];  // split-K partial (m, l)

// freq[e] = 10000^(-e/10) (both even/odd rows reduce to exponent e/10)
__constant__ double c_freq[NE] = {
    1.0,
    0.39810717055349725, 0.15848931924611134, 0.06309573444801933,
    0.025118864315095794, 0.01,
    0.0039810717055349725, 0.0015848931924611134, 0.0006309573444801933,
    0.00025118864315095795, 1e-4,
    3.9810717055349725e-05, 1.5848931924611134e-05, 6.309573444801933e-06,
    2.5118864315095795e-06, 1e-06,
    3.9810717055349725e-07, 1.5848931924611134e-07, 6.309573444801933e-08,
    2.5118864315095795e-08
};

// Fast exp2 via round-to-nearest magic constant + deg-5 Taylor on [-0.5,0.5].
// All fixed-latency 4-cycle ops (no F2I/floorf). Rel err ~3.4e-6.
// Valid for x in ~[-125, +90]; exact 1.0 at x==0.
__device__ __forceinline__ float exp2u(float x) {
    float z = __fadd_rn(x, 12582912.0f);             // 1.5*2^23: round-to-nearest int
    float f = __fsub_rn(x, __fsub_rn(z, 12582912.0f)); // f in [-0.5, 0.5]
    float p =            1.3333558e-3f;
    p = fmaf(p, f, 9.6181291e-3f);
    p = fmaf(p, f, 5.5504109e-2f);
    p = fmaf(p, f, 2.4022651e-1f);
    p = fmaf(p, f, 6.9314718e-1f);
    p = fmaf(p, f, 1.0f);
    return __int_as_float((__float_as_int(z) << 23) + 0x3F800000) * p;
}
__device__ __forceinline__ float exp2c(float x) { return exp2u(fmaxf(x, -125.0f)); }

// ---------------- conv embed + positional encoding ----------------
// z-dim = channel group of 4 -> 5x more blocks, 4 channels per thread
__global__ void conv_pe_kernel(const float* __restrict__ x, const float* __restrict__ w)
{
    __shared__ float ws[4*KW];
    __shared__ float xs[128 + KW - 1];
    int b  = blockIdx.y;
    int g  = blockIdx.z;           // channel group: e in [4g, 4g+4)
    int l0 = blockIdx.x * 128;
    int t  = threadIdx.x;
    for (int i = t; i < 4*KW; i += 128) ws[i] = w[g*4*KW + i];
    for (int i = t; i < 128 + KW - 1; i += 128) {
        int gi = l0 - CPAD + i;
        xs[i] = (gi >= 0 && gi < LSEQ) ? x[b*LSEQ + gi] : 0.f;
    }
    __syncthreads();
    int l = l0 + t;
    if (l >= LSEQ) return;

    float xr[KW];
    #pragma unroll
    for (int k = 0; k < KW; k++) xr[k] = xs[t + k];

    float* hrow = g_h + (b*LSEQ + l)*NE;
    double pos = (double)l;
    #pragma unroll
    for (int ee = 0; ee < 4; ee++) {
        int e = g*4 + ee;
        float a = 0.f, bacc = 0.f;
        #pragma unroll
        for (int k = 0; k < KW; k += 2) {
            a    = fmaf(xr[k],   ws[ee*KW + k],   a);
            bacc = fmaf(xr[k+1], ws[ee*KW + k+1], bacc);
        }
        // double-precision range reduction, then fp32 sin/cos
        double arg = pos * c_freq[e];
        double kq  = rint(arg * 0.15915494309189535);  // /(2*pi)
        float red  = (float)fma(kq, -6.283185307179586, arg);
        float pe   = (e & 1) ? cosf(red) : sinf(red);
        hrow[e] = (a + bacc) + pe;
    }
}

// ---------------- QKV projection (per-head 4x4), scale*log2e folded into Q ----------------
__global__ void qkv_kernel(const float* __restrict__ wq, const float* __restrict__ wk,
                           const float* __restrict__ wv)
{
    int idx = blockIdx.x * blockDim.x + threadIdx.x;
    if (idx >= NBH*LSEQ) return;
    int l  = idx % LSEQ;
    int bh = idx / LSEQ;       // b*NH + h
    int h  = bh % NH;
    int b  = bh / NH;

    const float4 s = *(const float4*)(g_h + (b*LSEQ + l)*NE + h*ND);
    const float QS = 0.32260195918f;  // log2(e)/sqrt(20)

    float qo[4], ko[4], vo[4];
    #pragma unroll
    for (int d = 0; d < 4; d++) {
        qo[d] = (s.x*wq[d*4+0] + s.y*wq[d*4+1] + s.z*wq[d*4+2] + s.w*wq[d*4+3]) * QS;
        ko[d] =  s.x*wk[d*4+0] + s.y*wk[d*4+1] + s.z*wk[d*4+2] + s.w*wk[d*4+3];
        vo[d] =  s.x*wv[d*4+0] + s.y*wv[d*4+1] + s.z*wv[d*4+2] + s.w*wv[d*4+3];
    }
    int off = (bh*LSEQ + l);
    ((float4*)g_q)[off] = make_float4(qo[0], qo[1], qo[2], qo[3]);
    ((float4*)g_k)[off] = make_float4(ko[0], ko[1], ko[2], ko[3]);
    ((float4*)g_v)[off] = make_float4(vo[0], vo[1], vo[2], vo[3]);
}

// ---------------- flash attention, split-K, branchless two-pass tiles ----------------
__global__ void __launch_bounds__(128) attn_kernel()
{
    __shared__ float4 ks[KCHUNK];   // 16 KB
    __shared__ float4 vs[KCHUNK];   // 16 KB
    int bh  = blockIdx.y;
    int ksp = blockIdx.z;
    int q0  = blockIdx.x * 128;
    int t   = threadIdx.x;
    int qi  = q0 + t;

    const float4* qp = ((const float4*)g_q) + bh*LSEQ;
    const float4* kp = ((const float4*)g_k) + bh*LSEQ + ksp*KCHUNK;
    const float4* vp = ((const float4*)g_v) + bh*LSEQ + ksp*KCHUNK;

    // stage entire K/V chunk in SMEM once (no per-tile barriers)
    for (int i = t; i < KCHUNK; i += 128) { ks[i] = kp[i]; vs[i] = vp[i]; }
    __syncthreads();

    float4 q = (qi < LSEQ) ? qp[qi] : make_float4(0.f, 0.f, 0.f, 0.f);
    float m = -1e30f, l = 0.f;
    float a0 = 0.f, a1 = 0.f, a2 = 0.f, a3 = 0.f;

    for (int kt = 0; kt < KCHUNK; kt += KTILE) {
        float s[KTILE];
        float mt0 = -1e30f, mt1 = -1e30f;
        // pass A: dots + tile max (branchless, full ILP)
        #pragma unroll
        for (int j = 0; j < KTILE; j++) {
            float4 kk = ks[kt + j];
            s[j] = fmaf(q.x, kk.x, fmaf(q.y, kk.y, fmaf(q.z, kk.z, q.w*kk.w)));
            if (j & 1) mt1 = fmaxf(mt1, s[j]); else mt0 = fmaxf(mt0, s[j]);
        }
        float mt = fmaxf(mt0, mt1);
        float newm = fmaxf(m, mt);
        float c = exp2c(m - newm);     // 1.0 when m unchanged; ~0 on first tile
        m = newm;
        l *= c; a0 *= c; a1 *= c; a2 *= c; a3 *= c;
        // pass B: exp + accumulate (branchless)
        #pragma unroll
        for (int j = 0; j < KTILE; j++) {
            float e = exp2u(s[j] - m);
            float4 vv = vs[kt + j];
            l += e;
            a0 = fmaf(e, vv.x, a0);
            a1 = fmaf(e, vv.y, a1);
            a2 = fmaf(e, vv.z, a2);
            a3 = fmaf(e, vv.w, a3);
        }
    }

    if (qi < LSEQ) {
        int idx = (bh*KSPLIT + ksp)*LSEQ + qi;
        g_pacc[idx] = make_float4(a0, a1, a2, a3);
        g_pml[idx]  = make_float2(m, l);
    }
}

// combine split-K partials -> g_o
__global__ void attn_combine_kernel()
{
    int idx = blockIdx.x * blockDim.x + threadIdx.x;  // bh*LSEQ + qi
    if (idx >= NBH*LSEQ) return;
    int bh = idx / LSEQ, qi = idx % LSEQ;

    float2 ml[KSPLIT]; float4 ac[KSPLIT];
    float M = -1e30f;
    #pragma unroll
    for (int p = 0; p < KSPLIT; p++) {
        int i = (bh*KSPLIT + p)*LSEQ + qi;
        ml[p] = g_pml[i]; ac[p] = g_pacc[i];
        M = fmaxf(M, ml[p].x);
    }
    float l = 0.f, a0 = 0.f, a1 = 0.f, a2 = 0.f, a3 = 0.f;
    #pragma unroll
    for (int p = 0; p < KSPLIT; p++) {
        float c = exp2c(ml[p].x - M);
        l  = fmaf(ml[p].y, c, l);
        a0 = fmaf(ac[p].x, c, a0);
        a1 = fmaf(ac[p].y, c, a1);
        a2 = fmaf(ac[p].z, c, a2);
        a3 = fmaf(ac[p].w, c, a3);
    }
    int b = bh / NH, h = bh % NH;
    float inv = 1.f / l;
    float* op = g_o + (b*LSEQ + qi)*NE + h*ND;
    *(float4*)op = make_float4(a0*inv, a1*inv, a2*inv, a3*inv);
}

// ---------------- fused: out-proj + residual + LN_A + FF + residual + LN_B ----------------
__global__ void proj_ff_kernel(const float* __restrict__ Wc, const float* __restrict__ bc,
                               const float* __restrict__ ga, const float* __restrict__ ba,
                               const float* __restrict__ W1, const float* __restrict__ b1,
                               const float* __restrict__ W2, const float* __restrict__ b2,
                               const float* __restrict__ gb, const float* __restrict__ bb)
{
    __shared__ float orow[NE], hrow[NE], h1[NE], hid[NFF], part[NFF];
    int row = blockIdx.x;
    int t   = threadIdx.x;
    if (t < NE) { orow[t] = g_o[row*NE + t]; hrow[t] = g_h[row*NE + t]; }
    __syncthreads();

    float tv = 0.f;
    if (t < NE) {
        float a = bc[t] + hrow[t], b = 0.f;
        #pragma unroll
        for (int e = 0; e < NE; e += 2) {
            a = fmaf(orow[e],   Wc[t*NE + e],   a);
            b = fmaf(orow[e+1], Wc[t*NE + e+1], b);
        }
        tv = a + b;
    }
    if (t < 32) {  // warp 0: LN over 20 values via shuffles
        float s = (t < NE) ? tv : 0.f;
        #pragma unroll
        for (int o = 16; o; o >>= 1) s += __shfl_xor_sync(0xffffffffu, s, o);
        float mu = s * (1.0f/NE);
        float d  = (t < NE) ? (tv - mu) : 0.f;
        float s2 = d * d;
        #pragma unroll
        for (int o = 16; o; o >>= 1) s2 += __shfl_xor_sync(0xffffffffu, s2, o);
        float rstd = rsqrtf(s2 * (1.0f/NE) + 1e-5f);
        if (t < NE) h1[t] = d * rstd * ga[t] + ba[t];
    }
    __syncthreads();

    if (t < NFF) {
        float a = b1[t], b = 0.f;
        #pragma unroll
        for (int e = 0; e < NE; e += 2) {
            a = fmaf(h1[e],   W1[t*NE + e],   a);
            b = fmaf(h1[e+1], W1[t*NE + e+1], b);
        }
        hid[t] = fmaxf(a + b, 0.f);
    }
    __syncthreads();

    // FF2: 6-way split partials (thread t: output t%20, slice t/20)
    if (t < NFF) {
        int o = t % NE, p = t / NE;
        const float* w  = W2 + o*NFF + p*20;
        const float* hh = hid + p*20;
        float a = 0.f, b = 0.f;
        #pragma unroll
        for (int f = 0; f < 20; f += 2) {
            a = fmaf(hh[f],   w[f],   a);
            b = fmaf(hh[f+1], w[f+1], b);
        }
        part[t] = a + b;
    }
    __syncthreads();

    if (t < 32) {
        float fv = 0.f;
        if (t < NE) {
            fv = b2[t] + h1[t]
               + ((part[t] + part[t+20]) + (part[t+40] + part[t+60]))
               + (part[t+80] + part[t+100]);
        }
        float s = (t < NE) ? fv : 0.f;
        #pragma unroll
        for (int o = 16; o; o >>= 1) s += __shfl_xor_sync(0xffffffffu, s, o);
        float mu = s * (1.0f/NE);
        float d  = (t < NE) ? (fv - mu) : 0.f;
        float s2 = d * d;
        #pragma unroll
        for (int o = 16; o; o >>= 1) s2 += __shfl_xor_sync(0xffffffffu, s2, o);
        float rstd = rsqrtf(s2 * (1.0f/NE) + 1e-5f);
        if (t < NE) g_h[row*NE + t] = d * rstd * gb[t] + bb[t];
    }
}

// ---------------- decoder MLP: 20 -> 40 -> 40 -> 20 -> 1 (sigmoid) ----------------
__global__ void dec_kernel(const float* __restrict__ f1w, const float* __restrict__ f1b,
                           const float* __restrict__ f2w, const float* __restrict__ f2b,
                           const float* __restrict__ f3w, const float* __restrict__ f3b,
                           const float* __restrict__ f4w, const float* __restrict__ f4b,
                           float* __restrict__ out)
{
    __shared__ float hrow[NE], d1[NDEC], d2[NDEC], d3s[NE];
    int row = blockIdx.x;
    int t   = threadIdx.x;
    if (t < NE) hrow[t] = g_h[row*NE + t];
    __syncthreads();
    if (t < NDEC) {
        float a = f1b[t], b = 0.f;
        #pragma unroll
        for (int e = 0; e < NE; e += 2) {
            a = fmaf(hrow[e],   f1w[t*NE + e],   a);
            b = fmaf(hrow[e+1], f1w[t*NE + e+1], b);
        }
        d1[t] = fmaxf(a + b, 0.f);
    }
    __syncthreads();
    if (t < NDEC) {
        float a = f2b[t], b = 0.f;
        #pragma unroll
        for (int j = 0; j < NDEC; j += 2) {
            a = fmaf(d1[j],   f2w[t*NDEC + j],   a);
            b = fmaf(d1[j+1], f2w[t*NDEC + j+1], b);
        }
        d2[t] = fmaxf(a + b, 0.f);
    }
    __syncthreads();
    if (t < NE) {
        float a = f3b[t], b = 0.f;
        #pragma unroll
        for (int j = 0; j < NDEC; j += 2) {
            a = fmaf(d2[j],   f3w[t*NDEC + j],   a);
            b = fmaf(d2[j+1], f3w[t*NDEC + j+1], b);
        }
        d3s[t] = fmaxf(a + b, 0.f);
    }
    __syncthreads();
    if (t == 0) {
        float a = f4b[0];
        #pragma unroll
        for (int e = 0; e < NE; e++) a = fmaf(d3s[e], f4w[e], a);
        out[row] = 1.f / (1.f + expf(-a));
    }
}

// ---------------- launch ----------------
extern "C" void kernel_launch(void* const* d_in, const int* in_sizes, int n_in,
                              void* d_out, int out_size)
{
    const float* x      = (const float*)d_in[0];
    const float* conv_w = (const float*)d_in[1];
    const float* Wv     = (const float*)d_in[2];
    const float* Wk     = (const float*)d_in[3];
    const float* Wq     = (const float*)d_in[4];
    const float* Wc     = (const float*)d_in[5];
    const float* bc     = (const float*)d_in[6];
    const float* lnAg   = (const float*)d_in[7];
    const float* lnAb   = (const float*)d_in[8];
    const float* W1     = (const float*)d_in[9];
    const float* b1     = (const float*)d_in[10];
    const float* W2     = (const float*)d_in[11];
    const float* b2     = (const float*)d_in[12];
    const float* lnBg   = (const float*)d_in[13];
    const float* lnBb   = (const float*)d_in[14];
    const float* f1w    = (const float*)d_in[15];
    const float* f1b    = (const float*)d_in[16];
    const float* f2w    = (const float*)d_in[17];
    const float* f2b    = (const float*)d_in[18];
    const float* f3w    = (const float*)d_in[19];
    const float* f3b    = (const float*)d_in[20];
    const float* f4w    = (const float*)d_in[21];
    const float* f4b    = (const float*)d_in[22];
    float* out = (float*)d_out;

    conv_pe_kernel<<<dim3((LSEQ + 127)/128, NB, 5), 128>>>(x, conv_w);
    for (int i = 0; i < 4; i++) {
        qkv_kernel<<<(NBH*LSEQ + 127)/128, 128>>>(Wq + i*16, Wk + i*16, Wv + i*16);
        attn_kernel<<<dim3((LSEQ + 127)/128, NBH, KSPLIT), 128>>>();
        attn_combine_kernel<<<(NBH*LSEQ + 127)/128, 128>>>();
        proj_ff_kernel<<<NB*LSEQ, 128>>>(Wc + i*NE*NE, bc + i*NE,
                                         lnAg + i*NE, lnAb + i*NE,
                                         W1 + i*NFF*NE, b1 + i*NFF,
                                         W2 + i*NE*NFF, b2 + i*NE,
                                         lnBg + i*NE, lnBb + i*NE);
    }
    dec_kernel<<<NB*LSEQ, 64>>>(f1w, f1b, f2w, f2b, f3w, f3b, f4w, f4b, out);
}

// round 16
// speedup vs baseline: 2.1500x; 1.0772x over previous
#include <cuda_runtime.h>
#include <math.h>

#define LSEQ 5000
#define NB 2
#define NE 20
#define NH 5
#define ND 4
#define NFF 120
#define NDEC 40
#define KW 50
#define CPAD 25
#define NBH (NB*NH)
#define KSPLIT 10
#define KCHUNK (LSEQ/KSPLIT)   // 500
#define KTILE 25               // KCHUNK % KTILE == 0
#define QPB 256                // queries per block (128 threads x 2)

typedef unsigned long long u64;

// ---------------- device scratch (no allocations allowed) ----------------
__device__ __align__(16) float g_h[NB*LSEQ*NE];          // residual stream (B,L,E)
__device__ __align__(16) float g_q[NBH*LSEQ*ND];         // (B,H,L,D)
__device__ __align__(16) float g_k[NBH*LSEQ*ND];
__device__ __align__(16) float g_v[NBH*LSEQ*ND];
__device__ __align__(16) float4 g_pacc[NBH*KSPLIT*LSEQ]; // split-K partial accumulators
__device__ __align__(16) float2 g_pml[NBH*KSPLIT*LSEQ];  // split-K partial (m, l)

// freq[e] = 10000^(-e/10)
__constant__ double c_freq[NE] = {
    1.0,
    0.39810717055349725, 0.15848931924611134, 0.06309573444801933,
    0.025118864315095794, 0.01,
    0.0039810717055349725, 0.0015848931924611134, 0.0006309573444801933,
    0.00025118864315095795, 1e-4,
    3.9810717055349725e-05, 1.5848931924611134e-05, 6.309573444801933e-06,
    2.5118864315095795e-06, 1e-06,
    3.9810717055349725e-07, 1.5848931924611134e-07, 6.309573444801933e-08,
    2.5118864315095795e-08
};

// ---------------- packed f32x2 helpers ----------------
__device__ __forceinline__ u64 pk2(float a, float b) {
    u64 r; asm("mov.b64 %0, {%1,%2};" : "=l"(r) : "f"(a), "f"(b)); return r;
}
__device__ __forceinline__ float2 upk(u64 v) {
    float2 f; asm("mov.b64 {%0,%1}, %2;" : "=f"(f.x), "=f"(f.y) : "l"(v)); return f;
}
__device__ __forceinline__ u64 fma2_(u64 a, u64 b, u64 c) {
    u64 d; asm("fma.rn.f32x2 %0, %1, %2, %3;" : "=l"(d) : "l"(a), "l"(b), "l"(c)); return d;
}
__device__ __forceinline__ u64 mul2_(u64 a, u64 b) {
    u64 d; asm("mul.rn.f32x2 %0, %1, %2;" : "=l"(d) : "l"(a), "l"(b)); return d;
}
__device__ __forceinline__ u64 add2_(u64 a, u64 b) {
    u64 d; asm("add.rn.f32x2 %0, %1, %2;" : "=l"(d) : "l"(a), "l"(b)); return d;
}
__device__ __forceinline__ u64 kdup(float f) {
    unsigned int b = __float_as_uint(f); return ((u64)b << 32) | b;
}

// scalar fast exp2 (deg-5, magic-constant rounding). Valid x in ~[-125, 90].
__device__ __forceinline__ float exp2u(float x) {
    float z = __fadd_rn(x, 12582912.0f);
    float f = __fsub_rn(x, __fsub_rn(z, 12582912.0f));
    float p =            1.3333558e-3f;
    p = fmaf(p, f, 9.6181291e-3f);
    p = fmaf(p, f, 5.5504109e-2f);
    p = fmaf(p, f, 2.4022651e-1f);
    p = fmaf(p, f, 6.9314718e-1f);
    p = fmaf(p, f, 1.0f);
    return __int_as_float((__float_as_int(z) << 23) + 0x3F800000) * p;
}
__device__ __forceinline__ float exp2c(float x) { return exp2u(fmaxf(x, -125.0f)); }

// packed exp2, deg-4 Taylor on [-0.5,0.5] (err ~6e-5). 8 fma-pipe ops for 2 lanes.
__device__ __forceinline__ u64 exp2x2(u64 x2) {
    const u64 MAGIC2 = kdup(12582912.0f);
    const u64 NEG1   = kdup(-1.0f);
    u64 z2 = add2_(x2, MAGIC2);
    u64 nz = fma2_(z2, NEG1, x2);        // x - z
    u64 f2 = add2_(nz, MAGIC2);          // x - (z - magic)
    u64 p2 = fma2_(kdup(9.6181291e-3f), f2, kdup(5.5504109e-2f));
    p2 = fma2_(p2, f2, kdup(2.4022651e-1f));
    p2 = fma2_(p2, f2, kdup(6.9314718e-1f));
    p2 = fma2_(p2, f2, kdup(1.0f));
    unsigned int zlo = (unsigned int)(z2 & 0xffffffffu);
    unsigned int zhi = (unsigned int)(z2 >> 32);
    unsigned int slo = (zlo << 23) + 0x3F800000u;
    unsigned int shi = (zhi << 23) + 0x3F800000u;
    u64 s2 = ((u64)shi << 32) | slo;
    return mul2_(p2, s2);
}

// ---------------- conv embed + positional encoding ----------------
__global__ void conv_pe_kernel(const float* __restrict__ x, const float* __restrict__ w)
{
    __shared__ float ws[4*KW];
    __shared__ float xs[128 + KW - 1];
    int b  = blockIdx.y;
    int g  = blockIdx.z;           // channel group: e in [4g, 4g+4)
    int l0 = blockIdx.x * 128;
    int t  = threadIdx.x;
    for (int i = t; i < 4*KW; i += 128) ws[i] = w[g*4*KW + i];
    for (int i = t; i < 128 + KW - 1; i += 128) {
        int gi = l0 - CPAD + i;
        xs[i] = (gi >= 0 && gi < LSEQ) ? x[b*LSEQ + gi] : 0.f;
    }
    __syncthreads();
    int l = l0 + t;
    if (l >= LSEQ) return;

    float xr[KW];
    #pragma unroll
    for (int k = 0; k < KW; k++) xr[k] = xs[t + k];

    float* hrow = g_h + (b*LSEQ + l)*NE;
    double pos = (double)l;
    #pragma unroll
    for (int ee = 0; ee < 4; ee++) {
        int e = g*4 + ee;
        float a = 0.f, bacc = 0.f;
        #pragma unroll
        for (int k = 0; k < KW; k += 2) {
            a    = fmaf(xr[k],   ws[ee*KW + k],   a);
            bacc = fmaf(xr[k+1], ws[ee*KW + k+1], bacc);
        }
        double arg = pos * c_freq[e];
        double kq  = rint(arg * 0.15915494309189535);
        float red  = (float)fma(kq, -6.283185307179586, arg);
        float pe   = (e & 1) ? cosf(red) : sinf(red);
        hrow[e] = (a + bacc) + pe;
    }
}

// ---------------- QKV projection, scale*log2e folded into Q ----------------
__global__ void qkv_kernel(const float* __restrict__ wq, const float* __restrict__ wk,
                           const float* __restrict__ wv)
{
    int idx = blockIdx.x * blockDim.x + threadIdx.x;
    if (idx >= NBH*LSEQ) return;
    int l  = idx % LSEQ;
    int bh = idx / LSEQ;
    int h  = bh % NH;
    int b  = bh / NH;

    const float4 s = *(const float4*)(g_h + (b*LSEQ + l)*NE + h*ND);
    const float QS = 0.32260195918f;  // log2(e)/sqrt(20)

    float qo[4], ko[4], vo[4];
    #pragma unroll
    for (int d = 0; d < 4; d++) {
        qo[d] = (s.x*wq[d*4+0] + s.y*wq[d*4+1] + s.z*wq[d*4+2] + s.w*wq[d*4+3]) * QS;
        ko[d] =  s.x*wk[d*4+0] + s.y*wk[d*4+1] + s.z*wk[d*4+2] + s.w*wk[d*4+3];
        vo[d] =  s.x*wv[d*4+0] + s.y*wv[d*4+1] + s.z*wv[d*4+2] + s.w*wv[d*4+3];
    }
    int off = (bh*LSEQ + l);
    ((float4*)g_q)[off] = make_float4(qo[0], qo[1], qo[2], qo[3]);
    ((float4*)g_k)[off] = make_float4(ko[0], ko[1], ko[2], ko[3]);
    ((float4*)g_v)[off] = make_float4(vo[0], vo[1], vo[2], vo[3]);
}

// ---------------- flash attention: split-K, f32x2-packed 2 queries/thread ----------------
union F4U { float4 f; u64 u[2]; };

__global__ void __launch_bounds__(128) attn_kernel()
{
    __shared__ float4 ks[KCHUNK*2];   // duplicated: (kx,kx,ky,ky),(kz,kz,kw,kw)  16KB
    __shared__ float4 vs[KCHUNK*2];   // 16KB
    int bh  = blockIdx.y;
    int ksp = blockIdx.z;
    int q0  = blockIdx.x * QPB;
    int t   = threadIdx.x;

    const float4* kp = ((const float4*)g_k) + bh*LSEQ + ksp*KCHUNK;
    const float4* vp = ((const float4*)g_v) + bh*LSEQ + ksp*KCHUNK;
    for (int i = t; i < KCHUNK; i += 128) {
        float4 k4 = kp[i];
        ks[2*i]   = make_float4(k4.x, k4.x, k4.y, k4.y);
        ks[2*i+1] = make_float4(k4.z, k4.z, k4.w, k4.w);
        float4 v4 = vp[i];
        vs[2*i]   = make_float4(v4.x, v4.x, v4.y, v4.y);
        vs[2*i+1] = make_float4(v4.z, v4.z, v4.w, v4.w);
    }
    __syncthreads();

    int qa = q0 + t, qb = q0 + 128 + t;
    const float4* qp = ((const float4*)g_q) + bh*LSEQ;
    float4 qA = (qa < LSEQ) ? qp[qa] : make_float4(0.f, 0.f, 0.f, 0.f);
    float4 qB = (qb < LSEQ) ? qp[qb] : make_float4(0.f, 0.f, 0.f, 0.f);
    u64 qx2 = pk2(qA.x, qB.x), qy2 = pk2(qA.y, qB.y);
    u64 qz2 = pk2(qA.z, qB.z), qw2 = pk2(qA.w, qB.w);

    float ma = -1e30f, mb = -1e30f;
    u64 l2 = 0, a0 = 0, a1 = 0, a2 = 0, a3 = 0;

    for (int kt = 0; kt < KCHUNK; kt += KTILE) {
        u64 s2[KTILE];
        float ma0 = -1e30f, ma1 = -1e30f, mb0 = -1e30f, mb1 = -1e30f;
        // pass A: packed dots + scalar tile max
        #pragma unroll
        for (int j = 0; j < KTILE; j++) {
            F4U kd0, kd1;
            kd0.f = ks[2*(kt + j)];
            kd1.f = ks[2*(kt + j) + 1];
            u64 d = mul2_(qw2, kd1.u[1]);
            d = fma2_(qz2, kd1.u[0], d);
            d = fma2_(qy2, kd0.u[1], d);
            d = fma2_(qx2, kd0.u[0], d);
            s2[j] = d;
            float2 sf = upk(d);
            if (j & 1) { ma1 = fmaxf(ma1, sf.x); mb1 = fmaxf(mb1, sf.y); }
            else       { ma0 = fmaxf(ma0, sf.x); mb0 = fmaxf(mb0, sf.y); }
        }
        float na = fmaxf(ma, fmaxf(ma0, ma1));
        float nb = fmaxf(mb, fmaxf(mb0, mb1));
        float ca = exp2u(fmaxf(ma - na, -125.f));
        float cb = exp2u(fmaxf(mb - nb, -125.f));
        u64 c2 = pk2(ca, cb);
        ma = na; mb = nb;
        l2 = mul2_(l2, c2);
        a0 = mul2_(a0, c2); a1 = mul2_(a1, c2);
        a2 = mul2_(a2, c2); a3 = mul2_(a3, c2);
        u64 negm2 = pk2(-na, -nb);
        // pass B: packed exp + accumulate
        #pragma unroll
        for (int j = 0; j < KTILE; j++) {
            u64 e2 = exp2x2(add2_(s2[j], negm2));
            F4U vd0, vd1;
            vd0.f = vs[2*(kt + j)];
            vd1.f = vs[2*(kt + j) + 1];
            l2 = add2_(l2, e2);
            a0 = fma2_(e2, vd0.u[0], a0);
            a1 = fma2_(e2, vd0.u[1], a1);
            a2 = fma2_(e2, vd1.u[0], a2);
            a3 = fma2_(e2, vd1.u[1], a3);
        }
    }

    float2 lf = upk(l2), A0 = upk(a0), A1 = upk(a1), A2 = upk(a2), A3 = upk(a3);
    int base = (bh*KSPLIT + ksp)*LSEQ;
    if (qa < LSEQ) {
        g_pacc[base + qa] = make_float4(A0.x, A1.x, A2.x, A3.x);
        g_pml[base + qa]  = make_float2(ma, lf.x);
    }
    if (qb < LSEQ) {
        g_pacc[base + qb] = make_float4(A0.y, A1.y, A2.y, A3.y);
        g_pml[base + qb]  = make_float2(mb, lf.y);
    }
}

// ---------------- fused: split-K combine + out-proj + LN_A + FF + LN_B ----------------
__global__ void proj_ff_kernel(const float* __restrict__ Wc, const float* __restrict__ bc,
                               const float* __restrict__ ga, const float* __restrict__ ba,
                               const float* __restrict__ W1, const float* __restrict__ b1,
                               const float* __restrict__ W2, const float* __restrict__ b2,
                               const float* __restrict__ gb, const float* __restrict__ bb)
{
    __shared__ float orow[NE], hrow[NE], h1[NE], hid[NFF], part[NFF];
    int row = blockIdx.x;
    int t   = threadIdx.x;
    int l   = row % LSEQ, b = row / LSEQ;

    // split-K combine prelude: thread t<NH merges KSPLIT partials for head t
    if (t < NH) {
        int base = (b*NH + t)*KSPLIT;
        float mv[KSPLIT];
        float M = -1e30f;
        #pragma unroll
        for (int p = 0; p < KSPLIT; p++) {
            mv[p] = g_pml[(base + p)*LSEQ + l].x;
            M = fmaxf(M, mv[p]);
        }
        float L = 0.f, A0 = 0.f, A1 = 0.f, A2 = 0.f, A3 = 0.f;
        #pragma unroll
        for (int p = 0; p < KSPLIT; p++) {
            int i = (base + p)*LSEQ + l;
            float c = exp2u(fmaxf(mv[p] - M, -125.f));
            float lp = g_pml[i].y;
            float4 a = g_pacc[i];
            L  = fmaf(lp, c, L);
            A0 = fmaf(a.x, c, A0); A1 = fmaf(a.y, c, A1);
            A2 = fmaf(a.z, c, A2); A3 = fmaf(a.w, c, A3);
        }
        float inv = 1.f / L;
        orow[t*4+0] = A0*inv; orow[t*4+1] = A1*inv;
        orow[t*4+2] = A2*inv; orow[t*4+3] = A3*inv;
    }
    if (t < NE) hrow[t] = g_h[row*NE + t];
    __syncthreads();

    float tv = 0.f;
    if (t < NE) {
        float a = bc[t] + hrow[t], bx = 0.f;
        #pragma unroll
        for (int e = 0; e < NE; e += 2) {
            a  = fmaf(orow[e],   Wc[t*NE + e],   a);
            bx = fmaf(orow[e+1], Wc[t*NE + e+1], bx);
        }
        tv = a + bx;
    }
    if (t < 32) {
        float s = (t < NE) ? tv : 0.f;
        #pragma unroll
        for (int o = 16; o; o >>= 1) s += __shfl_xor_sync(0xffffffffu, s, o);
        float mu = s * (1.0f/NE);
        float d  = (t < NE) ? (tv - mu) : 0.f;
        float s2 = d * d;
        #pragma unroll
        for (int o = 16; o; o >>= 1) s2 += __shfl_xor_sync(0xffffffffu, s2, o);
        float rstd = rsqrtf(s2 * (1.0f/NE) + 1e-5f);
        if (t < NE) h1[t] = d * rstd * ga[t] + ba[t];
    }
    __syncthreads();

    if (t < NFF) {
        float a = b1[t], bx = 0.f;
        #pragma unroll
        for (int e = 0; e < NE; e += 2) {
            a  = fmaf(h1[e],   W1[t*NE + e],   a);
            bx = fmaf(h1[e+1], W1[t*NE + e+1], bx);
        }
        hid[t] = fmaxf(a + bx, 0.f);
    }
    __syncthreads();

    if (t < NFF) {
        int o = t % NE, p = t / NE;
        const float* w  = W2 + o*NFF + p*20;
        const float* hh = hid + p*20;
        float a = 0.f, bx = 0.f;
        #pragma unroll
        for (int f = 0; f < 20; f += 2) {
            a  = fmaf(hh[f],   w[f],   a);
            bx = fmaf(hh[f+1], w[f+1], bx);
        }
        part[t] = a + bx;
    }
    __syncthreads();

    if (t < 32) {
        float fv = 0.f;
        if (t < NE) {
            fv = b2[t] + h1[t]
               + ((part[t] + part[t+20]) + (part[t+40] + part[t+60]))
               + (part[t+80] + part[t+100]);
        }
        float s = (t < NE) ? fv : 0.f;
        #pragma unroll
        for (int o = 16; o; o >>= 1) s += __shfl_xor_sync(0xffffffffu, s, o);
        float mu = s * (1.0f/NE);
        float d  = (t < NE) ? (fv - mu) : 0.f;
        float s2 = d * d;
        #pragma unroll
        for (int o = 16; o; o >>= 1) s2 += __shfl_xor_sync(0xffffffffu, s2, o);
        float rstd = rsqrtf(s2 * (1.0f/NE) + 1e-5f);
        if (t < NE) g_h[row*NE + t] = d * rstd * gb[t] + bb[t];
    }
}

// ---------------- decoder MLP: 20 -> 40 -> 40 -> 20 -> 1 (sigmoid) ----------------
__global__ void dec_kernel(const float* __restrict__ f1w, const float* __restrict__ f1b,
                           const float* __restrict__ f2w, const float* __restrict__ f2b,
                           const float* __restrict__ f3w, const float* __restrict__ f3b,
                           const float* __restrict__ f4w, const float* __restrict__ f4b,
                           float* __restrict__ out)
{
    __shared__ float hrow[NE], d1[NDEC], d2[NDEC], d3s[NE];
    int row = blockIdx.x;
    int t   = threadIdx.x;
    if (t < NE) hrow[t] = g_h[row*NE + t];
    __syncthreads();
    if (t < NDEC) {
        float a = f1b[t], bx = 0.f;
        #pragma unroll
        for (int e = 0; e < NE; e += 2) {
            a  = fmaf(hrow[e],   f1w[t*NE + e],   a);
            bx = fmaf(hrow[e+1], f1w[t*NE + e+1], bx);
        }
        d1[t] = fmaxf(a + bx, 0.f);
    }
    __syncthreads();
    if (t < NDEC) {
        float a = f2b[t], bx = 0.f;
        #pragma unroll
        for (int j = 0; j < NDEC; j += 2) {
            a  = fmaf(d1[j],   f2w[t*NDEC + j],   a);
            bx = fmaf(d1[j+1], f2w[t*NDEC + j+1], bx);
        }
        d2[t] = fmaxf(a + bx, 0.f);
    }
    __syncthreads();
    if (t < NE) {
        float a = f3b[t], bx = 0.f;
        #pragma unroll
        for (int j = 0; j < NDEC; j += 2) {
            a  = fmaf(d2[j],   f3w[t*NDEC + j],   a);
            bx = fmaf(d2[j+1], f3w[t*NDEC + j+1], bx);
        }
        d3s[t] = fmaxf(a + bx, 0.f);
    }
    __syncthreads();
    if (t == 0) {
        float a = f4b[0];
        #pragma unroll
        for (int e = 0; e < NE; e++) a = fmaf(d3s[e], f4w[e], a);
        out[row] = 1.f / (1.f + expf(-a));
    }
}

// ---------------- launch ----------------
extern "C" void kernel_launch(void* const* d_in, const int* in_sizes, int n_in,
                              void* d_out, int out_size)
{
    const float* x      = (const float*)d_in[0];
    const float* conv_w = (const float*)d_in[1];
    const float* Wv     = (const float*)d_in[2];
    const float* Wk     = (const float*)d_in[3];
    const float* Wq     = (const float*)d_in[4];
    const float* Wc     = (const float*)d_in[5];
    const float* bc     = (const float*)d_in[6];
    const float* lnAg   = (const float*)d_in[7];
    const float* lnAb   = (const float*)d_in[8];
    const float* W1     = (const float*)d_in[9];
    const float* b1     = (const float*)d_in[10];
    const float* W2     = (const float*)d_in[11];
    const float* b2     = (const float*)d_in[12];
    const float* lnBg   = (const float*)d_in[13];
    const float* lnBb   = (const float*)d_in[14];
    const float* f1w    = (const float*)d_in[15];
    const float* f1b    = (const float*)d_in[16];
    const float* f2w    = (const float*)d_in[17];
    const float* f2b    = (const float*)d_in[18];
    const float* f3w    = (const float*)d_in[19];
    const float* f3b    = (const float*)d_in[20];
    const float* f4w    = (const float*)d_in[21];
    const float* f4b    = (const float*)d_in[22];
    float* out = (float*)d_out;

    conv_pe_kernel<<<dim3((LSEQ + 127)/128, NB, 5), 128>>>(x, conv_w);
    for (int i = 0; i < 4; i++) {
        qkv_kernel<<<(NBH*LSEQ + 127)/128, 128>>>(Wq + i*16, Wk + i*16, Wv + i*16);
        attn_kernel<<<dim3((LSEQ + QPB - 1)/QPB, NBH, KSPLIT), 128>>>();
        proj_ff_kernel<<<NB*LSEQ, 128>>>(Wc + i*NE*NE, bc + i*NE,
                                         lnAg + i*NE, lnAb + i*NE,
                                         W1 + i*NFF*NE, b1 + i*NFF,
                                         W2 + i*NE*NFF, b2 + i*NE,
                                         lnBg + i*NE, lnBb + i*NE);
    }
    dec_kernel<<<NB*LSEQ, 64>>>(f1w, f1b, f2w, f2b, f3w, f3b, f4w, f4b, out);
}